// round 6
// baseline (speedup 1.0000x reference)
#include <cuda_runtime.h>
#include <cuda_fp16.h>
#include <math.h>

#define FULL 0xffffffffu
#define B_ 8192
#define T_ 256
#define K_ 16
#define LOG2E 1.4426950408889634f
#define LN2   0.6931471805599453f

__device__ unsigned g_codes32[B_*64];   // 1 byte/step {m:2, t1:4, (t==0,1: t0 bits):2}
__device__ float    g_goldtr2[B_*2];    // two partial gold sums per seq

static __device__ __forceinline__ float ex2f_(float x){ float r; asm("ex2.approx.ftz.f32 %0,%1;":"=f"(r):"f"(x)); return r; }
static __device__ __forceinline__ float lg2f_(float x){ float r; asm("lg2.approx.ftz.f32 %0,%1;":"=f"(r):"f"(x)); return r; }
static __device__ __forceinline__ __half2 u2h(unsigned u){ return *reinterpret_cast<__half2*>(&u); }

// ---------------- pass 1: pack codes + gold parts (warp per half-sequence) ----------------
__global__ __launch_bounds__(256)
void pack_kernel(const int* __restrict__ tags, const int* __restrict__ w2w,
                 const int* __restrict__ icnt, const int* __restrict__ dist,
                 const float* __restrict__ cw, const float* __restrict__ trans,
                 const float* __restrict__ start)
{
    __shared__ float TR[1024];
    int tid = threadIdx.x;
    for (int i = tid; i < 1024; i += 256) TR[i] = trans[i];
    __syncthreads();

    int wp = tid >> 5, lane = tid & 31;
    int seq  = blockIdx.x*4 + (wp >> 1);
    int half = wp & 1;
    const int* tg = tags + seq*T_;
    float gsum = 0.f;

    #pragma unroll 1
    for (int c = 0; c < 4; ++c) {
        int t = half*128 + c*32 + lane;
        unsigned byte;
        if (t < 255) {
            int a  = w2w [seq*(T_-1)+t];
            int ic = icnt[seq*(T_-1)+t];
            int di = dist[seq*(T_-1)+t];
            int m = (a==1) ? 0 : ((ic==0) ? 1 : ((di==0) ? 2 : 3));
            int t0 = tg[t], t1 = tg[t+1];
            gsum += __ldg(&cw[t1]) * TR[(m*16+t0)*16+t1];
            byte = (unsigned)m | ((unsigned)t1 << 2);
            if (t == 0) byte |= ((unsigned)tg[0] & 3u) << 6;
            if (t == 1) byte |= (((unsigned)tg[0] >> 2) & 3u) << 6;
        } else {                       // t == 255: start-score gold part
            int t0 = tg[0];
            gsum += __ldg(&cw[t0]) * __ldg(&start[t0]);
            byte = 0;
        }
        unsigned v = byte << ((lane & 3)*8);
        v |= __shfl_xor_sync(FULL, v, 1);
        v |= __shfl_xor_sync(FULL, v, 2);
        if ((lane & 3) == 0)
            g_codes32[seq*64 + half*32 + c*8 + (lane >> 2)] = v;
    }
    gsum += __shfl_xor_sync(FULL, gsum, 16);
    gsum += __shfl_xor_sync(FULL, gsum, 8);
    gsum += __shfl_xor_sync(FULL, gsum, 4);
    gsum += __shfl_xor_sync(FULL, gsum, 2);
    gsum += __shfl_xor_sync(FULL, gsum, 1);
    if (lane == 0) g_goldtr2[seq*2 + half] = gsum;
}

// ---------------- pass 2: linear-domain CRF, lane-per-tag, 2 seqs per lane ----------------
__global__ __launch_bounds__(64)
void crf_main(const float* __restrict__ em, const float* __restrict__ cw,
              const float* __restrict__ trans, const float* __restrict__ start,
              float* __restrict__ out)
{
    __shared__ __align__(16) __half ETT[4*384];     // exp(trans)^T, 48B column stride
    __shared__ __align__(16) __half PS[2][2][2][32]; // [warp][buf][AB][lane]

    int tid = threadIdx.x;
    #pragma unroll
    for (int k = 0; k < 16; ++k) {
        int idx = tid + k*64;                        // trans[m][i][jj]
        int m = idx >> 8, i = (idx >> 4) & 15, jj = idx & 15;
        ETT[m*384 + jj*24 + i] = __float2half_rn(expf(trans[idx]));
    }
    __syncthreads();

    int warp = tid >> 5, lane = tid & 31, h = lane >> 4, j = lane & 15;
    int sA = (blockIdx.x*2 + warp)*2 + h;
    int sB = sA + B_/2;

    const float* peA = em + (size_t)sA*(T_*K_) + j;
    const float* peB = em + (size_t)sB*(T_*K_) + j;
    const uint2* pcA = reinterpret_cast<const uint2*>(g_codes32 + sA*64);
    const uint2* pcB = reinterpret_cast<const uint2*>(g_codes32 + sB*64);
    const char* ettc = reinterpret_cast<const char*>(ETT);
    unsigned jrow = (unsigned)(j*48);

    float wj = __ldg(&cw[j]);
    float sj = __ldg(&start[j]);
    float e0A = peA[0], e0B = peB[0];

    uint2 cCA = pcA[0], cNA = pcA[1];
    uint2 cCB = pcB[0], cNB = pcB[1];
    int t0A = (int)((cCA.x >> 6) & 3u) | ((int)((cCA.x >> 14) & 3u) << 2);
    int t0B = (int)((cCB.x >> 6) & 3u) | ((int)((cCB.x >> 14) & 3u) << 2);

    float aA = ex2f_((sj + e0A) * LOG2E);
    float aB = ex2f_((sj + e0B) * LOG2E);
    float goldA = (j == t0A) ? wj * e0A : 0.f;
    float goldB = (j == t0B) ? wj * e0B : 0.f;

    // initial exact power-of-2 normalization (applied now, logged in ksum)
    float s0A = __shfl_sync(FULL, aA, 0, 16);
    float s0B = __shfl_sync(FULL, aB, 0, 16);
    unsigned biA0 = __float_as_uint(s0A), biB0 = __float_as_uint(s0B);
    int ksumA = (int)(biA0 >> 23) - 121;
    int ksumB = (int)(biB0 >> 23) - 121;
    float pfA = aA * __uint_as_float(0x7C000000u - (biA0 & 0x7f800000u));
    float pfB = aB * __uint_as_float(0x7C000000u - (biB0 & 0x7f800000u));
    __half phA = __float2half_rn(pfA);
    __half phB = __float2half_rn(pfB);
    float spA = __shfl_sync(FULL, pfA, 0, 16);   // lagged exponent source
    float spB = __shfl_sync(FULL, pfB, 0, 16);

    float ebA[8], ebB[8];
    #pragma unroll
    for (int r = 0; r < 8; ++r) { ebA[r] = peA[(r+1)*K_]; ebB[r] = peB[(r+1)*K_]; }

#define STEP2(WA, WB, SH, SIDX, RI, BF) do {                                    \
    unsigned bA_ = ((WA) >> (SH)) & 0xffu, bB_ = ((WB) >> (SH)) & 0xffu;        \
    float eA_ = ebA[RI]; ebA[RI] = peA[min((SIDX)+9, 255)*K_];                  \
    float eB_ = ebB[RI]; ebB[RI] = peB[min((SIDX)+9, 255)*K_];                  \
    PS[warp][BF][0][lane] = phA;                                                \
    PS[warp][BF][1][lane] = phB;                                                \
    __syncwarp();                                                               \
    unsigned biA_ = __float_as_uint(spA); ksumA += (int)(biA_ >> 23) - 121;     \
    float scA_ = __uint_as_float(0x7C000000u - (biA_ & 0x7f800000u));           \
    float eescA_ = ex2f_(eA_ * LOG2E) * scA_;                                   \
    unsigned biB_ = __float_as_uint(spB); ksumB += (int)(biB_ >> 23) - 121;     \
    float scB_ = __uint_as_float(0x7C000000u - (biB_ & 0x7f800000u));           \
    float eescB_ = ex2f_(eB_ * LOG2E) * scB_;                                   \
    const uint4* evA_ = reinterpret_cast<const uint4*>(ettc + (bA_&3u)*768u + jrow); \
    const uint4* evB_ = reinterpret_cast<const uint4*>(ettc + (bB_&3u)*768u + jrow); \
    uint4 EA0_ = evA_[0], EA1_ = evA_[1];                                       \
    uint4 EB0_ = evB_[0], EB1_ = evB_[1];                                       \
    const uint4* pvA_ = reinterpret_cast<const uint4*>(&PS[warp][BF][0][h*16]); \
    const uint4* pvB_ = reinterpret_cast<const uint4*>(&PS[warp][BF][1][h*16]); \
    uint4 PA0_ = pvA_[0], PA1_ = pvA_[1];                                       \
    uint4 PB0_ = pvB_[0], PB1_ = pvB_[1];                                       \
    __half2 xA_ = __hmul2(u2h(PA0_.x), u2h(EA0_.x));                            \
    __half2 yA_ = __hmul2(u2h(PA0_.y), u2h(EA0_.y));                            \
    xA_ = __hfma2(u2h(PA0_.z), u2h(EA0_.z), xA_);                               \
    yA_ = __hfma2(u2h(PA0_.w), u2h(EA0_.w), yA_);                               \
    xA_ = __hfma2(u2h(PA1_.x), u2h(EA1_.x), xA_);                               \
    yA_ = __hfma2(u2h(PA1_.y), u2h(EA1_.y), yA_);                               \
    xA_ = __hfma2(u2h(PA1_.z), u2h(EA1_.z), xA_);                               \
    yA_ = __hfma2(u2h(PA1_.w), u2h(EA1_.w), yA_);                               \
    xA_ = __hadd2(xA_, yA_);                                                    \
    __half2 xB_ = __hmul2(u2h(PB0_.x), u2h(EB0_.x));                            \
    __half2 yB_ = __hmul2(u2h(PB0_.y), u2h(EB0_.y));                            \
    xB_ = __hfma2(u2h(PB0_.z), u2h(EB0_.z), xB_);                               \
    yB_ = __hfma2(u2h(PB0_.w), u2h(EB0_.w), yB_);                               \
    xB_ = __hfma2(u2h(PB1_.x), u2h(EB1_.x), xB_);                               \
    yB_ = __hfma2(u2h(PB1_.y), u2h(EB1_.y), yB_);                               \
    xB_ = __hfma2(u2h(PB1_.z), u2h(EB1_.z), xB_);                               \
    yB_ = __hfma2(u2h(PB1_.w), u2h(EB1_.w), yB_);                               \
    xB_ = __hadd2(xB_, yB_);                                                    \
    float2 fA_ = __half22float2(xA_);                                           \
    float2 fB_ = __half22float2(xB_);                                           \
    pfA = (fA_.x + fA_.y) * eescA_;                                             \
    pfB = (fB_.x + fB_.y) * eescB_;                                             \
    phA = __float2half_rn(pfA);                                                 \
    phB = __float2half_rn(pfB);                                                 \
    spA = __shfl_sync(FULL, pfA, 0, 16);                                        \
    spB = __shfl_sync(FULL, pfB, 0, 16);                                        \
    if ((unsigned)j == ((bA_ >> 2) & 15u)) goldA = fmaf(wj, eA_, goldA);        \
    if ((unsigned)j == ((bB_ >> 2) & 15u)) goldB = fmaf(wj, eB_, goldB);        \
} while (0)

    #pragma unroll 1
    for (int chunk = 0; chunk < 31; ++chunk) {
        int base = chunk*8;
        unsigned wA0 = cCA.x, wA1 = cCA.y, wB0 = cCB.x, wB1 = cCB.y;
        STEP2(wA0, wB0,  0, base+0, (base+0)&7, 0);
        STEP2(wA0, wB0,  8, base+1, (base+1)&7, 1);
        STEP2(wA0, wB0, 16, base+2, (base+2)&7, 0);
        STEP2(wA0, wB0, 24, base+3, (base+3)&7, 1);
        STEP2(wA1, wB1,  0, base+4, (base+4)&7, 0);
        STEP2(wA1, wB1,  8, base+5, (base+5)&7, 1);
        STEP2(wA1, wB1, 16, base+6, (base+6)&7, 0);
        STEP2(wA1, wB1, 24, base+7, (base+7)&7, 1);
        cCA = cNA; cNA = pcA[min(chunk+2, 31)];
        cCB = cNB; cNB = pcB[min(chunk+2, 31)];
    }
    // epilogue: chunk 31 = steps 248..254 (7 steps; byte for step 255 unused)
    {
        unsigned wA0 = cCA.x, wA1 = cCA.y, wB0 = cCB.x, wB1 = cCB.y;
        STEP2(wA0, wB0,  0, 248, 0, 0);
        STEP2(wA0, wB0,  8, 249, 1, 1);
        STEP2(wA0, wB0, 16, 250, 2, 0);
        STEP2(wA0, wB0, 24, 251, 3, 1);
        STEP2(wA1, wB1,  0, 252, 4, 0);
        STEP2(wA1, wB1,  8, 253, 5, 1);
        STEP2(wA1, wB1, 16, 254, 6, 0);
    }
#undef STEP2

    // logZ = ln2 * (log2(sum_j p_j) + ksum)
    float zA = pfA, zB = pfB;
    zA += __shfl_xor_sync(FULL, zA, 8, 16);
    zA += __shfl_xor_sync(FULL, zA, 4, 16);
    zA += __shfl_xor_sync(FULL, zA, 2, 16);
    zA += __shfl_xor_sync(FULL, zA, 1, 16);
    zB += __shfl_xor_sync(FULL, zB, 8, 16);
    zB += __shfl_xor_sync(FULL, zB, 4, 16);
    zB += __shfl_xor_sync(FULL, zB, 2, 16);
    zB += __shfl_xor_sync(FULL, zB, 1, 16);
    float logZA = LN2 * (lg2f_(zA) + (float)ksumA);
    float logZB = LN2 * (lg2f_(zB) + (float)ksumB);

    float gA = goldA, gB = goldB;
    gA += __shfl_xor_sync(FULL, gA, 8, 16);
    gA += __shfl_xor_sync(FULL, gA, 4, 16);
    gA += __shfl_xor_sync(FULL, gA, 2, 16);
    gA += __shfl_xor_sync(FULL, gA, 1, 16);
    gB += __shfl_xor_sync(FULL, gB, 8, 16);
    gB += __shfl_xor_sync(FULL, gB, 4, 16);
    gB += __shfl_xor_sync(FULL, gB, 2, 16);
    gB += __shfl_xor_sync(FULL, gB, 1, 16);

    if (j == 0) {
        out[sA]      = gA + g_goldtr2[sA*2] + g_goldtr2[sA*2+1];
        out[B_ + sA] = logZA;
        out[sB]      = gB + g_goldtr2[sB*2] + g_goldtr2[sB*2+1];
        out[B_ + sB] = logZB;
    }
}

extern "C" void kernel_launch(void* const* d_in, const int* in_sizes, int n_in,
                              void* d_out, int out_size) {
    const float* em    = (const float*)d_in[0];
    const int*   tags  = (const int*)d_in[1];
    const int*   w2w   = (const int*)d_in[2];
    const int*   icnt  = (const int*)d_in[3];
    const int*   dist  = (const int*)d_in[4];
    const float* cw    = (const float*)d_in[5];
    const float* trans = (const float*)d_in[6];
    const float* start = (const float*)d_in[7];
    float* out = (float*)d_out;

    pack_kernel<<<B_/4, 256>>>(tags, w2w, icnt, dist, cw, trans, start);
    crf_main<<<B_/8, 64>>>(em, cw, trans, start, out);
}